// round 17
// baseline (speedup 1.0000x reference)
#include <cuda_runtime.h>
#include <cuda_bf16.h>
#include <cstdint>

// Problem constants (shapes fixed by setup_inputs)
#define HW      (1024 * 1024)             // pixels per channel
#define NBINS   16
#define NTOT    (NBINS * NBINS * NBINS)   // 4096
#define NPAIR   (NTOT / 2)                // 2048 paired (64-bit) bins
#define NIMG    9                         // 8 input images + 1 style image
#define BPI     115                       // blocks per image (9*115=1035 <= 148*7)
#define TPB     256                       // threads per block
#define NCTA    (BPI * NIMG)              // 1035 CTAs (single wave @ 7/SM, 32KB)

#define LOSS_CTAS  16
#define LOSS_TPB   128                    // 16*128 = 2048 = NPAIR threads

// Global scratch (zero-initialized at module load; loss kernel re-zeros its
// own state after each use, so every graph replay sees clean state).
__device__ unsigned long long g_hist2[NIMG][NPAIR];
__device__ unsigned int       g_loss_acc;   // exact integer L1 sum
__device__ unsigned int       g_done;       // ticket for last-CTA detection

// Bin permutation for bank spreading: low 4 bits become (r+g+b) mod 16
// (3-fold mod-16 convolution flattens the Gaussian channel-bin spikes).
// Bijective within each 16-bin row.
__device__ __forceinline__ int sbin(int f) {
    return (f & ~15) | ((f + (f >> 4) + (f >> 8)) & 15);
}

// searchsorted(boundaries, v, side='left') with boundaries = i/8 - 1, i=1..15.
// = count of boundaries strictly < v = clamp(ceil(8*(v+1)) - 1, 0, 15).
__device__ __forceinline__ int bin_of(float v) {
    int i = __float2int_ru(fmaf(v, 8.0f, 8.0f)) - 1;   // single F2I.CEIL
    i = max(i, 0);
    i = min(i, 15);
    return i;
}

__device__ __forceinline__ int flat_bin(float r, float g, float b) {
    return bin_of(r) + (bin_of(g) << 4) + (bin_of(b) << 8);
}

// ---------------------------------------------------------------------------
// Kernel A: per-image histogram with 2 lane-parity-sliced sub-histograms.
// word = 2*sbin(f) + (lane&1): even and odd lanes can never conflict, and
// within a 16-lane parity group banks are spread by the mixed low-4 of sbin
// (E[max 16->16] ~= 2.7 vs E[max 32->32] ~= 3.3).
// grid = (BPI, NIMG), block = TPB, 32 KB static smem (7 CTAs/SM).
// ---------------------------------------------------------------------------
__global__ __launch_bounds__(TPB) void hist_kernel(
    const float* __restrict__ inp,   // [8, 3, H, W]
    const float* __restrict__ sty)   // [1, 3, H, W]
{
    __shared__ int sh[2 * NTOT];     // 32 KB: two slots per bin
    #pragma unroll
    for (int i = threadIdx.x; i < 2 * NTOT; i += TPB) sh[i] = 0;
    __syncthreads();

    const int img  = blockIdx.y;
    const int par  = threadIdx.x & 1;           // lane parity -> slot
    const float* base = (img < 8) ? (inp + (size_t)img * 3 * HW) : sty;

    const float4* r4 = (const float4*)(base);
    const float4* g4 = (const float4*)(base + HW);
    const float4* b4 = (const float4*)(base + 2 * HW);

    const int nvec      = HW / 4;                    // 262144 float4/channel
    const int per_block = (nvec + BPI - 1) / BPI;    // 2280
    const int start     = blockIdx.x * per_block;
    const int end       = min(start + per_block, nvec);

    #pragma unroll 2
    for (int i = start + threadIdx.x; i < end; i += TPB) {
        float4 r = r4[i];
        float4 g = g4[i];
        float4 b = b4[i];

        atomicAdd(&sh[2 * sbin(flat_bin(r.x, g.x, b.x)) + par], 1);
        atomicAdd(&sh[2 * sbin(flat_bin(r.y, g.y, b.y)) + par], 1);
        atomicAdd(&sh[2 * sbin(flat_bin(r.z, g.z, b.z)) + par], 1);
        atomicAdd(&sh[2 * sbin(flat_bin(r.w, g.w, b.w)) + par], 1);
    }
    __syncthreads();

    // Flush: sum the two slots per bin, pack two adjacent f-bins into one
    // 64-bit atomic (pruned on zero).
    #pragma unroll
    for (int fp = threadIdx.x; fp < NPAIR; fp += TPB) {
        const int w0 = 2 * sbin(2 * fp);
        const int w1 = 2 * sbin(2 * fp + 1);
        unsigned int lo = (unsigned int)sh[w0] + (unsigned int)sh[w0 + 1];
        unsigned int hi = (unsigned int)sh[w1] + (unsigned int)sh[w1 + 1];
        if (lo | hi) {
            atomicAdd(&g_hist2[img][fp],
                      (unsigned long long)lo | ((unsigned long long)hi << 32));
        }
    }
}

// ---------------------------------------------------------------------------
// Kernel B: parallel loss + scratch reset (round-8 proven config).
// grid = LOSS_CTAS, block = LOSS_TPB; one 64-bit pair index per thread.
// ---------------------------------------------------------------------------
__global__ __launch_bounds__(LOSS_TPB) void loss_kernel(float* __restrict__ out)
{
    const int i = blockIdx.x * LOSS_TPB + threadIdx.x;   // pair index, < NPAIR

    // 9 independent loads (batched for MLP)
    unsigned long long ps = g_hist2[8][i];
    unsigned long long p0 = g_hist2[0][i];
    unsigned long long p1 = g_hist2[1][i];
    unsigned long long p2 = g_hist2[2][i];
    unsigned long long p3 = g_hist2[3][i];
    unsigned long long p4 = g_hist2[4][i];
    unsigned long long p5 = g_hist2[5][i];
    unsigned long long p6 = g_hist2[6][i];
    unsigned long long p7 = g_hist2[7][i];

    int slo = (int)(unsigned int)ps;
    int shi = (int)(unsigned int)(ps >> 32);

    int acc = 0;   // max 2*8*HW = 16.8M < 2^31
    #define ABS_DIFF(p) do {                                   \
        int d0 = (int)(unsigned int)(p) - slo;                 \
        int d1 = (int)(unsigned int)((p) >> 32) - shi;         \
        acc += (d0 < 0 ? -d0 : d0) + (d1 < 0 ? -d1 : d1);      \
    } while (0)
    ABS_DIFF(p0); ABS_DIFF(p1); ABS_DIFF(p2); ABS_DIFF(p3);
    ABS_DIFF(p4); ABS_DIFF(p5); ABS_DIFF(p6); ABS_DIFF(p7);
    #undef ABS_DIFF

    // reset this thread's slice of the scratch for the next graph replay
    #pragma unroll
    for (int b = 0; b < NIMG; b++) g_hist2[b][i] = 0ULL;

    // block reduction
    #pragma unroll
    for (int o = 16; o > 0; o >>= 1)
        acc += __shfl_xor_sync(0xffffffffu, acc, o);

    __shared__ int warp_sum[LOSS_TPB / 32];
    if ((threadIdx.x & 31) == 0) warp_sum[threadIdx.x >> 5] = acc;
    __syncthreads();

    __shared__ unsigned int my_ticket;
    if (threadIdx.x == 0) {
        int blk = 0;
        #pragma unroll
        for (int w = 0; w < LOSS_TPB / 32; w++) blk += warp_sum[w];
        atomicAdd(&g_loss_acc, (unsigned int)blk);
        __threadfence();
        my_ticket = atomicAdd(&g_done, 1u);
    }
    __syncthreads();

    if (threadIdx.x == 0 && my_ticket == (unsigned int)(LOSS_CTAS - 1)) {
        unsigned int total = atomicAdd(&g_loss_acc, 0u);   // coherent read
        out[0] = (float)((double)total /
                         ((double)HW * 8.0 * (double)NTOT));
        g_loss_acc = 0u;
        g_done = 0u;
    }
}

// ---------------------------------------------------------------------------
// Launch contract
// ---------------------------------------------------------------------------
extern "C" void kernel_launch(void* const* d_in, const int* in_sizes, int n_in,
                              void* d_out, int out_size)
{
    const float* inp = (const float*)d_in[0];   // [8,3,1024,1024] fp32
    const float* sty = (const float*)d_in[1];   // [1,3,1024,1024] fp32
    float* out = (float*)d_out;

    dim3 grid(BPI, NIMG);
    hist_kernel<<<grid, TPB>>>(inp, sty);
    loss_kernel<<<LOSS_CTAS, LOSS_TPB>>>(out);
}